// round 7
// baseline (speedup 1.0000x reference)
#include <cuda_runtime.h>
#include <float.h>

#define N_REF   500000
#define N_PC    128
#define N_FEAT  2000
#define TOP_K   16

#define BLOCKS           592
#define THREADS          256
#define WARPS_PER_BLOCK  (THREADS / 32)
#define TOTAL_WARPS      (BLOCKS * WARPS_PER_BLOCK)   // 4736
#define N_CAND           (BLOCKS * TOP_K)             // 9472
#define M1_BLOCKS        37                           // 37*256 = 9472 exactly
#define N_CAND2          (M1_BLOCKS * TOP_K)          // 592

#define PROJ_BLOCKS      50
#define FEAT_PER_BLOCK   (N_FEAT / PROJ_BLOCKS)       // 40

// Scratch (no cudaMalloc allowed)
__device__ float g_qpart[PROJ_BLOCKS * N_PC];
__device__ float g_cand_d[N_CAND];
__device__ int   g_cand_i[N_CAND];
__device__ float g_cand2_d[N_CAND2];
__device__ int   g_cand2_i[N_CAND2];

// ---------------------------------------------------------------------------
// Branch-free register top-16 insert (lane 0 of streaming warps only; rare
// and hidden behind DRAM latency).
// ---------------------------------------------------------------------------
__device__ __forceinline__ void bubble_insert(float (&d)[TOP_K], int (&ix)[TOP_K],
                                              float v, int id) {
    #pragma unroll
    for (int t = 0; t < TOP_K; t++) {
        bool sw  = v < d[t];
        float tv = d[t];
        int   ti = ix[t];
        d[t]  = sw ? v  : tv;
        ix[t] = sw ? id : ti;
        v     = sw ? tv : v;
        id    = sw ? ti : id;
    }
}

// ---------------------------------------------------------------------------
// Full bitonic sort of 32 (v,i) pairs across a warp (ascending by lane).
// ---------------------------------------------------------------------------
__device__ __forceinline__ void bitonic32(float& v, int& i, int lane) {
    #pragma unroll
    for (int k = 2; k <= 32; k <<= 1) {
        #pragma unroll
        for (int j = k >> 1; j > 0; j >>= 1) {
            float ov = __shfl_xor_sync(0xFFFFFFFFu, v, j);
            int   oi = __shfl_xor_sync(0xFFFFFFFFu, i, j);
            bool up      = ((lane & k) == 0);
            bool lower   = ((lane & j) == 0);
            bool takeMin = (lower == up);
            bool sel = takeMin ? (ov < v) : (ov > v);
            v = sel ? ov : v;
            i = sel ? oi : i;
        }
    }
}

// ---------------------------------------------------------------------------
// Kernel A: partial query projection (block b covers 40 features).
// ---------------------------------------------------------------------------
__global__ void project_partial(const float* __restrict__ data_in,
                                const float* __restrict__ tmat) {
    int j  = threadIdx.x;
    int b  = blockIdx.x;
    int k0 = b * FEAT_PER_BLOCK;
    float acc = 0.0f;
    #pragma unroll 8
    for (int k = k0; k < k0 + FEAT_PER_BLOCK; k++)
        acc += data_in[k] * tmat[k * N_PC + j];
    g_qpart[b * N_PC + j] = acc;
}

// ---------------------------------------------------------------------------
// Kernel B: [prologue] finish query reduction per-block (L2-hot, ~free)
//           [mainloop] streaming L1 distance, warp/row, 4-row unroll,
//                      reduce-4 shuffle scheme (14 SHFL vs 20)
//           [tail] parallel rank-select block top-16.
// ---------------------------------------------------------------------------
__global__ void __launch_bounds__(THREADS)
dist_topk_kernel(const float* __restrict__ ref) {
    const int tid  = threadIdx.x;
    const int lane = tid & 31;
    const int wid  = tid >> 5;
    const int gw   = blockIdx.x * WARPS_PER_BLOCK + wid;

    // ---- prologue: reduce 50 projection partials -> shared query ----
    __shared__ float sq[N_PC];
    if (tid < N_PC) {
        float acc = 0.0f;
        #pragma unroll
        for (int b = 0; b < PROJ_BLOCKS; b++)
            acc += g_qpart[b * N_PC + tid];
        sq[tid] = acc;
    }
    __syncthreads();
    const float4 q = reinterpret_cast<const float4*>(sq)[lane];

    const int chunk = (N_REF + TOTAL_WARPS - 1) / TOTAL_WARPS;  // 106
    int start = gw * chunk;
    int end   = start + chunk;
    if (start > N_REF) start = N_REF;
    if (end   > N_REF) end   = N_REF;

    float topd[TOP_K];
    int   topi[TOP_K];
    #pragma unroll
    for (int t = 0; t < TOP_K; t++) { topd[t] = FLT_MAX; topi[t] = 0; }
    float kmax = FLT_MAX;

    const float4* __restrict__ ref4 = reinterpret_cast<const float4*>(ref);

    int r = start;
    for (; r + 4 <= end; r += 4) {
        float4 a0 = __ldcs(ref4 + (size_t)(r + 0) * (N_PC / 4) + lane);
        float4 a1 = __ldcs(ref4 + (size_t)(r + 1) * (N_PC / 4) + lane);
        float4 a2 = __ldcs(ref4 + (size_t)(r + 2) * (N_PC / 4) + lane);
        float4 a3 = __ldcs(ref4 + (size_t)(r + 3) * (N_PC / 4) + lane);

        float s0 = fabsf(a0.x - q.x) + fabsf(a0.y - q.y) + fabsf(a0.z - q.z) + fabsf(a0.w - q.w);
        float s1 = fabsf(a1.x - q.x) + fabsf(a1.y - q.y) + fabsf(a1.z - q.z) + fabsf(a1.w - q.w);
        float s2 = fabsf(a2.x - q.x) + fabsf(a2.y - q.y) + fabsf(a2.z - q.z) + fabsf(a2.w - q.w);
        float s3 = fabsf(a3.x - q.x) + fabsf(a3.y - q.y) + fabsf(a3.z - q.z) + fabsf(a3.w - q.w);

        // reduce-4: 2 butterfly stages on all four sums...
        s0 += __shfl_xor_sync(0xFFFFFFFFu, s0, 16);
        s1 += __shfl_xor_sync(0xFFFFFFFFu, s1, 16);
        s2 += __shfl_xor_sync(0xFFFFFFFFu, s2, 16);
        s3 += __shfl_xor_sync(0xFFFFFFFFu, s3, 16);
        s0 += __shfl_xor_sync(0xFFFFFFFFu, s0, 8);
        s1 += __shfl_xor_sync(0xFFFFFFFFu, s1, 8);
        s2 += __shfl_xor_sync(0xFFFFFFFFu, s2, 8);
        s3 += __shfl_xor_sync(0xFFFFFFFFu, s3, 8);
        // ...quarter q owns row q...
        int   qs = lane >> 3;
        float v  = (qs == 0) ? s0 : (qs == 1) ? s1 : (qs == 2) ? s2 : s3;
        // ...3 stages inside the 8-lane group complete the row sum
        v += __shfl_xor_sync(0xFFFFFFFFu, v, 4);
        v += __shfl_xor_sync(0xFFFFFFFFu, v, 2);
        v += __shfl_xor_sync(0xFFFFFFFFu, v, 1);
        // collect the 4 row sums at lane 0
        float r1 = __shfl_sync(0xFFFFFFFFu, v, 8);
        float r2 = __shfl_sync(0xFFFFFFFFu, v, 16);
        float r3 = __shfl_sync(0xFFFFFFFFu, v, 24);

        if (lane == 0) {
            if (v  < kmax) { bubble_insert(topd, topi, v,  r + 0); kmax = topd[TOP_K - 1]; }
            if (r1 < kmax) { bubble_insert(topd, topi, r1, r + 1); kmax = topd[TOP_K - 1]; }
            if (r2 < kmax) { bubble_insert(topd, topi, r2, r + 2); kmax = topd[TOP_K - 1]; }
            if (r3 < kmax) { bubble_insert(topd, topi, r3, r + 3); kmax = topd[TOP_K - 1]; }
        }
    }
    for (; r < end; r++) {
        float4 a0 = __ldcs(ref4 + (size_t)r * (N_PC / 4) + lane);
        float s0 = fabsf(a0.x - q.x) + fabsf(a0.y - q.y) + fabsf(a0.z - q.z) + fabsf(a0.w - q.w);
        #pragma unroll
        for (int off = 16; off > 0; off >>= 1)
            s0 += __shfl_xor_sync(0xFFFFFFFFu, s0, off);
        if (lane == 0 && s0 < kmax) {
            bubble_insert(topd, topi, s0, r);
            kmax = topd[TOP_K - 1];
        }
    }

    // ---- tail: parallel rank-select block top-16 over 128 shared entries ----
    __shared__ float sbd[WARPS_PER_BLOCK * TOP_K];   // 128
    __shared__ int   sbi[WARPS_PER_BLOCK * TOP_K];
    if (lane == 0) {
        #pragma unroll
        for (int t = 0; t < TOP_K; t++) {
            sbd[wid * TOP_K + t] = topd[t];
            sbi[wid * TOP_K + t] = topi[t];
        }
    }
    __syncthreads();

    if (tid < 128) {
        float v  = sbd[tid];
        int   id = sbi[tid];
        int rank = 0;
        #pragma unroll 8
        for (int j = 0; j < 128; j++) {
            float o = sbd[j];
            rank += (o < v) || (o == v && j < tid);
        }
        if (rank < TOP_K) {
            g_cand_d[blockIdx.x * TOP_K + rank] = v;
            g_cand_i[blockIdx.x * TOP_K + rank] = id;
        }
    }
}

// ---------------------------------------------------------------------------
// Kernel C1: 37 blocks x 256 threads; 1 candidate/thread.
// warp bitonic sort-32 -> top-16/warp -> 128 shared -> rank-select top-16.
// 9472 -> 592 candidates.
// ---------------------------------------------------------------------------
__global__ void merge1_kernel() {
    const int tid  = threadIdx.x;
    const int lane = tid & 31;
    const int wid  = tid >> 5;

    int c = blockIdx.x * 256 + tid;           // 37*256 == N_CAND exactly
    float v  = g_cand_d[c];
    int   id = g_cand_i[c];

    bitonic32(v, id, lane);

    __shared__ float sd[WARPS_PER_BLOCK * TOP_K];   // 128
    __shared__ int   si[WARPS_PER_BLOCK * TOP_K];
    if (lane < TOP_K) {
        sd[wid * TOP_K + lane] = v;
        si[wid * TOP_K + lane] = id;
    }
    __syncthreads();

    if (tid < 128) {
        float vv = sd[tid];
        int   ii = si[tid];
        int rank = 0;
        #pragma unroll 8
        for (int j = 0; j < 128; j++) {
            float o = sd[j];
            rank += (o < vv) || (o == vv && j < tid);
        }
        if (rank < TOP_K) {
            g_cand2_d[blockIdx.x * TOP_K + rank] = vv;
            g_cand2_i[blockIdx.x * TOP_K + rank] = ii;
        }
    }
}

// ---------------------------------------------------------------------------
// Kernel C2: 1 block x 608 threads; direct rank-select top-16 of 592,
// gather psuedo, mean.
// ---------------------------------------------------------------------------
__global__ void merge2_kernel(const float* __restrict__ psuedo,
                              float* __restrict__ out) {
    const int tid = threadIdx.x;

    __shared__ float sd[N_CAND2];
    __shared__ int   si[N_CAND2];
    __shared__ float s_sel[TOP_K];

    if (tid < N_CAND2) {
        sd[tid] = g_cand2_d[tid];
        si[tid] = g_cand2_i[tid];
    }
    __syncthreads();

    if (tid < N_CAND2) {
        float v = sd[tid];
        int rank = 0;
        #pragma unroll 8
        for (int j = 0; j < N_CAND2; j++) {
            float o = sd[j];
            rank += (o < v) || (o == v && j < tid);
        }
        if (rank < TOP_K) s_sel[rank] = psuedo[si[tid]];
    }
    __syncthreads();

    if (tid < 32) {
        float v = (tid < TOP_K) ? s_sel[tid] : 0.0f;
        #pragma unroll
        for (int off = 16; off > 0; off >>= 1)
            v += __shfl_xor_sync(0xFFFFFFFFu, v, off);
        if (tid == 0) out[0] = v * (1.0f / TOP_K);
    }
}

// ---------------------------------------------------------------------------
// Launch (4 kernels)
// ---------------------------------------------------------------------------
extern "C" void kernel_launch(void* const* d_in, const int* in_sizes, int n_in,
                              void* d_out, int out_size) {
    const float* data_in = (const float*)d_in[0];
    const float* tmat    = (const float*)d_in[1];
    const float* ref     = (const float*)d_in[2];
    const float* psuedo  = (const float*)d_in[3];
    float* out = (float*)d_out;

    project_partial<<<PROJ_BLOCKS, N_PC>>>(data_in, tmat);
    dist_topk_kernel<<<BLOCKS, THREADS>>>(ref);
    merge1_kernel<<<M1_BLOCKS, 256>>>();
    merge2_kernel<<<1, 608>>>(psuedo, out);
}

// round 8
// speedup vs baseline: 1.8676x; 1.8676x over previous
#include <cuda_runtime.h>
#include <float.h>

#define N_REF   500000
#define N_PC    128
#define N_FEAT  2000
#define TOP_K   16

#define BLOCKS           592
#define THREADS          256
#define WARPS_PER_BLOCK  (THREADS / 32)
#define TOTAL_WARPS      (BLOCKS * WARPS_PER_BLOCK)   // 4736
#define N_CAND           (BLOCKS * TOP_K)             // 9472
#define M1_BLOCKS        37                           // 37*256 = 9472 exactly
#define N_CAND2          (M1_BLOCKS * TOP_K)          // 592
#define N_CAND3          (19 * TOP_K)                 // 304 after warp pre-filter

#define PROJ_BLOCKS      50
#define FEAT_PER_BLOCK   (N_FEAT / PROJ_BLOCKS)       // 40

// Scratch (no cudaMalloc allowed)
__device__ float g_qpart[PROJ_BLOCKS * N_PC];
__device__ float g_query[N_PC];
__device__ float g_cand_d[N_CAND];
__device__ int   g_cand_i[N_CAND];
__device__ float g_cand2_d[N_CAND2];
__device__ int   g_cand2_i[N_CAND2];

// ---------------------------------------------------------------------------
// Branch-free register top-16 insert (lane 0 of streaming warps only; rare
// and hidden behind DRAM latency).
// ---------------------------------------------------------------------------
__device__ __forceinline__ void bubble_insert(float (&d)[TOP_K], int (&ix)[TOP_K],
                                              float v, int id) {
    #pragma unroll
    for (int t = 0; t < TOP_K; t++) {
        bool sw  = v < d[t];
        float tv = d[t];
        int   ti = ix[t];
        d[t]  = sw ? v  : tv;
        ix[t] = sw ? id : ti;
        v     = sw ? tv : v;
        id    = sw ? ti : id;
    }
}

// ---------------------------------------------------------------------------
// Full bitonic sort of 32 (v,i) pairs across a warp (ascending by lane).
// ---------------------------------------------------------------------------
__device__ __forceinline__ void bitonic32(float& v, int& i, int lane) {
    #pragma unroll
    for (int k = 2; k <= 32; k <<= 1) {
        #pragma unroll
        for (int j = k >> 1; j > 0; j >>= 1) {
            float ov = __shfl_xor_sync(0xFFFFFFFFu, v, j);
            int   oi = __shfl_xor_sync(0xFFFFFFFFu, i, j);
            bool up      = ((lane & k) == 0);
            bool lower   = ((lane & j) == 0);
            bool takeMin = (lower == up);
            bool sel = takeMin ? (ov < v) : (ov > v);
            v = sel ? ov : v;
            i = sel ? oi : i;
        }
    }
}

// ---------------------------------------------------------------------------
// Kernel A1/A2: query projection (split 50 ways, then reduce) — R4 config.
// ---------------------------------------------------------------------------
__global__ void project_partial(const float* __restrict__ data_in,
                                const float* __restrict__ tmat) {
    int j  = threadIdx.x;
    int b  = blockIdx.x;
    int k0 = b * FEAT_PER_BLOCK;
    float acc = 0.0f;
    #pragma unroll 8
    for (int k = k0; k < k0 + FEAT_PER_BLOCK; k++)
        acc += data_in[k] * tmat[k * N_PC + j];
    g_qpart[b * N_PC + j] = acc;
}

__global__ void project_reduce() {
    int j = threadIdx.x;
    float acc = 0.0f;
    #pragma unroll
    for (int b = 0; b < PROJ_BLOCKS; b++) acc += g_qpart[b * N_PC + j];
    g_query[j] = acc;
}

// ---------------------------------------------------------------------------
// Kernel B: streaming L1 distance. R6 body (4-row unroll, independent
// 5-stage butterfly chains) + NEW register double-buffer prefetch so the
// next 4 loads are in flight while the current 4 rows run the shuffle chain.
// Tail: parallel rank-select block top-16.
// ---------------------------------------------------------------------------
__global__ void __launch_bounds__(THREADS)
dist_topk_kernel(const float* __restrict__ ref) {
    const int tid  = threadIdx.x;
    const int lane = tid & 31;
    const int wid  = tid >> 5;
    const int gw   = blockIdx.x * WARPS_PER_BLOCK + wid;

    const float4 q = reinterpret_cast<const float4*>(g_query)[lane];

    const int chunk = (N_REF + TOTAL_WARPS - 1) / TOTAL_WARPS;  // 106
    int start = gw * chunk;
    int end   = start + chunk;
    if (start > N_REF) start = N_REF;
    if (end   > N_REF) end   = N_REF;

    float topd[TOP_K];
    int   topi[TOP_K];
    #pragma unroll
    for (int t = 0; t < TOP_K; t++) { topd[t] = FLT_MAX; topi[t] = 0; }
    float kmax = FLT_MAX;

    const float4* __restrict__ ref4 = reinterpret_cast<const float4*>(ref);

    const int nIter = (end - start) / 4;
    int r = start;

    float4 A0, A1, A2, A3;
    if (nIter > 0) {
        A0 = __ldcs(ref4 + (size_t)(r + 0) * (N_PC / 4) + lane);
        A1 = __ldcs(ref4 + (size_t)(r + 1) * (N_PC / 4) + lane);
        A2 = __ldcs(ref4 + (size_t)(r + 2) * (N_PC / 4) + lane);
        A3 = __ldcs(ref4 + (size_t)(r + 3) * (N_PC / 4) + lane);
    }

    for (int it = 0; it < nIter; it++) {
        // prefetch next 4 rows while current 4 are processed
        float4 B0, B1, B2, B3;
        if (it + 1 < nIter) {
            int rn = r + 4;
            B0 = __ldcs(ref4 + (size_t)(rn + 0) * (N_PC / 4) + lane);
            B1 = __ldcs(ref4 + (size_t)(rn + 1) * (N_PC / 4) + lane);
            B2 = __ldcs(ref4 + (size_t)(rn + 2) * (N_PC / 4) + lane);
            B3 = __ldcs(ref4 + (size_t)(rn + 3) * (N_PC / 4) + lane);
        }

        float s0 = fabsf(A0.x - q.x) + fabsf(A0.y - q.y) + fabsf(A0.z - q.z) + fabsf(A0.w - q.w);
        float s1 = fabsf(A1.x - q.x) + fabsf(A1.y - q.y) + fabsf(A1.z - q.z) + fabsf(A1.w - q.w);
        float s2 = fabsf(A2.x - q.x) + fabsf(A2.y - q.y) + fabsf(A2.z - q.z) + fabsf(A2.w - q.w);
        float s3 = fabsf(A3.x - q.x) + fabsf(A3.y - q.y) + fabsf(A3.z - q.z) + fabsf(A3.w - q.w);

        #pragma unroll
        for (int off = 16; off > 0; off >>= 1) {
            s0 += __shfl_xor_sync(0xFFFFFFFFu, s0, off);
            s1 += __shfl_xor_sync(0xFFFFFFFFu, s1, off);
            s2 += __shfl_xor_sync(0xFFFFFFFFu, s2, off);
            s3 += __shfl_xor_sync(0xFFFFFFFFu, s3, off);
        }

        if (lane == 0) {
            if (s0 < kmax) { bubble_insert(topd, topi, s0, r + 0); kmax = topd[TOP_K - 1]; }
            if (s1 < kmax) { bubble_insert(topd, topi, s1, r + 1); kmax = topd[TOP_K - 1]; }
            if (s2 < kmax) { bubble_insert(topd, topi, s2, r + 2); kmax = topd[TOP_K - 1]; }
            if (s3 < kmax) { bubble_insert(topd, topi, s3, r + 3); kmax = topd[TOP_K - 1]; }
        }

        A0 = B0; A1 = B1; A2 = B2; A3 = B3;
        r += 4;
    }
    // tail rows
    for (; r < end; r++) {
        float4 a0 = __ldcs(ref4 + (size_t)r * (N_PC / 4) + lane);
        float s0 = fabsf(a0.x - q.x) + fabsf(a0.y - q.y) + fabsf(a0.z - q.z) + fabsf(a0.w - q.w);
        #pragma unroll
        for (int off = 16; off > 0; off >>= 1)
            s0 += __shfl_xor_sync(0xFFFFFFFFu, s0, off);
        if (lane == 0 && s0 < kmax) {
            bubble_insert(topd, topi, s0, r);
            kmax = topd[TOP_K - 1];
        }
    }

    // ---- tail: parallel rank-select block top-16 over 128 shared entries ----
    __shared__ float sbd[WARPS_PER_BLOCK * TOP_K];   // 128
    __shared__ int   sbi[WARPS_PER_BLOCK * TOP_K];
    if (lane == 0) {
        #pragma unroll
        for (int t = 0; t < TOP_K; t++) {
            sbd[wid * TOP_K + t] = topd[t];
            sbi[wid * TOP_K + t] = topi[t];
        }
    }
    __syncthreads();

    if (tid < 128) {
        float v  = sbd[tid];
        int   id = sbi[tid];
        int rank = 0;
        #pragma unroll 8
        for (int j = 0; j < 128; j++) {
            float o = sbd[j];
            rank += (o < v) || (o == v && j < tid);
        }
        if (rank < TOP_K) {
            g_cand_d[blockIdx.x * TOP_K + rank] = v;
            g_cand_i[blockIdx.x * TOP_K + rank] = id;
        }
    }
}

// ---------------------------------------------------------------------------
// Kernel C1: 37 blocks x 256 threads; 1 candidate/thread.
// warp bitonic sort-32 -> top-16/warp -> 128 shared -> rank-select top-16.
// 9472 -> 592 candidates. (R4's measured-good merge1.)
// ---------------------------------------------------------------------------
__global__ void merge1_kernel() {
    const int tid  = threadIdx.x;
    const int lane = tid & 31;
    const int wid  = tid >> 5;

    int c = blockIdx.x * 256 + tid;           // 37*256 == N_CAND exactly
    float v  = g_cand_d[c];
    int   id = g_cand_i[c];

    bitonic32(v, id, lane);

    __shared__ float sd[WARPS_PER_BLOCK * TOP_K];   // 128
    __shared__ int   si[WARPS_PER_BLOCK * TOP_K];
    if (lane < TOP_K) {
        sd[wid * TOP_K + lane] = v;
        si[wid * TOP_K + lane] = id;
    }
    __syncthreads();

    if (tid < 128) {
        float vv = sd[tid];
        int   ii = si[tid];
        int rank = 0;
        #pragma unroll 8
        for (int j = 0; j < 128; j++) {
            float o = sd[j];
            rank += (o < vv) || (o == vv && j < tid);
        }
        if (rank < TOP_K) {
            g_cand2_d[blockIdx.x * TOP_K + rank] = vv;
            g_cand2_i[blockIdx.x * TOP_K + rank] = ii;
        }
    }
}

// ---------------------------------------------------------------------------
// Kernel C2: 1 block x 608 threads. Warp bitonic pre-filter (592 -> 304),
// then rank-select top-16 of 304, gather psuedo, mean.
// ---------------------------------------------------------------------------
__global__ void merge2_kernel(const float* __restrict__ psuedo,
                              float* __restrict__ out) {
    const int tid  = threadIdx.x;
    const int lane = tid & 31;
    const int wid  = tid >> 5;   // 0..18

    __shared__ float sd[N_CAND3];   // 304
    __shared__ int   si[N_CAND3];
    __shared__ float s_sel[TOP_K];

    // warp pre-filter: 19 warps cover 608 slots (last 16 padded)
    {
        bool ok = (tid < N_CAND2);
        float v  = ok ? g_cand2_d[tid] : FLT_MAX;
        int   id = ok ? g_cand2_i[tid] : 0;
        bitonic32(v, id, lane);
        if (lane < TOP_K) {
            sd[wid * TOP_K + lane] = v;
            si[wid * TOP_K + lane] = id;
        }
    }
    __syncthreads();

    if (tid < N_CAND3) {
        float v = sd[tid];
        int rank = 0;
        #pragma unroll 8
        for (int j = 0; j < N_CAND3; j++) {
            float o = sd[j];
            rank += (o < v) || (o == v && j < tid);
        }
        if (rank < TOP_K) s_sel[rank] = psuedo[si[tid]];
    }
    __syncthreads();

    if (tid < 32) {
        float v = (tid < TOP_K) ? s_sel[tid] : 0.0f;
        #pragma unroll
        for (int off = 16; off > 0; off >>= 1)
            v += __shfl_xor_sync(0xFFFFFFFFu, v, off);
        if (tid == 0) out[0] = v * (1.0f / TOP_K);
    }
}

// ---------------------------------------------------------------------------
// Launch (5 kernels)
// ---------------------------------------------------------------------------
extern "C" void kernel_launch(void* const* d_in, const int* in_sizes, int n_in,
                              void* d_out, int out_size) {
    const float* data_in = (const float*)d_in[0];
    const float* tmat    = (const float*)d_in[1];
    const float* ref     = (const float*)d_in[2];
    const float* psuedo  = (const float*)d_in[3];
    float* out = (float*)d_out;

    project_partial<<<PROJ_BLOCKS, N_PC>>>(data_in, tmat);
    project_reduce<<<1, N_PC>>>();
    dist_topk_kernel<<<BLOCKS, THREADS>>>(ref);
    merge1_kernel<<<M1_BLOCKS, 256>>>();
    merge2_kernel<<<1, 608>>>(psuedo, out);
}

// round 10
// speedup vs baseline: 1.9174x; 1.0266x over previous
#include <cuda_runtime.h>
#include <float.h>

#define N_REF   500000
#define N_PC    128
#define N_FEAT  2000
#define TOP_K   16

#define BLOCKS           592
#define THREADS          256
#define WARPS_PER_BLOCK  (THREADS / 32)
#define TOTAL_WARPS      (BLOCKS * WARPS_PER_BLOCK)   // 4736
#define N_CAND           (BLOCKS * TOP_K)             // 9472

#define PROJ_BLOCKS      50
#define FEAT_PER_BLOCK   (N_FEAT / PROJ_BLOCKS)       // 40

#define MERGE_T          1024
#define SURV_CAP         2048
#define MIN_PAD          608                          // 19 warps * 32
#define MIN_KEEP         304                          // 19 * 16

// Scratch (no cudaMalloc allowed)
__device__ float g_qpart[PROJ_BLOCKS * N_PC];
__device__ float g_query[N_PC];
__device__ float g_cand_d[N_CAND];
__device__ int   g_cand_i[N_CAND];

// ---------------------------------------------------------------------------
// Branch-free register top-16 insert (lane 0 of streaming warps only; rare
// and hidden behind DRAM latency).
// ---------------------------------------------------------------------------
__device__ __forceinline__ void bubble_insert(float (&d)[TOP_K], int (&ix)[TOP_K],
                                              float v, int id) {
    #pragma unroll
    for (int t = 0; t < TOP_K; t++) {
        bool sw  = v < d[t];
        float tv = d[t];
        int   ti = ix[t];
        d[t]  = sw ? v  : tv;
        ix[t] = sw ? id : ti;
        v     = sw ? tv : v;
        id    = sw ? ti : id;
    }
}

// ---------------------------------------------------------------------------
// Warp bitonic sort of 32 floats (ascending by lane), values only.
// ---------------------------------------------------------------------------
__device__ __forceinline__ void bitonic32v(float& v, int lane) {
    #pragma unroll
    for (int k = 2; k <= 32; k <<= 1) {
        #pragma unroll
        for (int j = k >> 1; j > 0; j >>= 1) {
            float ov = __shfl_xor_sync(0xFFFFFFFFu, v, j);
            bool up      = ((lane & k) == 0);
            bool lower   = ((lane & j) == 0);
            bool takeMin = (lower == up);
            bool sel = takeMin ? (ov < v) : (ov > v);
            v = sel ? ov : v;
        }
    }
}

// ---------------------------------------------------------------------------
// Kernel A1/A2: query projection (split 50 ways, then reduce)
// ---------------------------------------------------------------------------
__global__ void project_partial(const float* __restrict__ data_in,
                                const float* __restrict__ tmat) {
    int j  = threadIdx.x;
    int b  = blockIdx.x;
    int k0 = b * FEAT_PER_BLOCK;
    float acc = 0.0f;
    #pragma unroll 8
    for (int k = k0; k < k0 + FEAT_PER_BLOCK; k++)
        acc += data_in[k] * tmat[k * N_PC + j];
    g_qpart[b * N_PC + j] = acc;
}

__global__ void project_reduce() {
    int j = threadIdx.x;
    float acc = 0.0f;
    #pragma unroll
    for (int b = 0; b < PROJ_BLOCKS; b++) acc += g_qpart[b * N_PC + j];
    g_query[j] = acc;
}

// ---------------------------------------------------------------------------
// Kernel B (UNCHANGED from R8 best): streaming L1 distance, warp/row,
// 4-row unroll + register double-buffer prefetch; parallel rank-select tail.
// Rank-select writes each block's top-16 SORTED ascending (rank order) —
// rank 0 is the block MINIMUM; the merge threshold depends on this.
// ---------------------------------------------------------------------------
__global__ void __launch_bounds__(THREADS)
dist_topk_kernel(const float* __restrict__ ref) {
    const int tid  = threadIdx.x;
    const int lane = tid & 31;
    const int wid  = tid >> 5;
    const int gw   = blockIdx.x * WARPS_PER_BLOCK + wid;

    const float4 q = reinterpret_cast<const float4*>(g_query)[lane];

    const int chunk = (N_REF + TOTAL_WARPS - 1) / TOTAL_WARPS;  // 106
    int start = gw * chunk;
    int end   = start + chunk;
    if (start > N_REF) start = N_REF;
    if (end   > N_REF) end   = N_REF;

    float topd[TOP_K];
    int   topi[TOP_K];
    #pragma unroll
    for (int t = 0; t < TOP_K; t++) { topd[t] = FLT_MAX; topi[t] = 0; }
    float kmax = FLT_MAX;

    const float4* __restrict__ ref4 = reinterpret_cast<const float4*>(ref);

    const int nIter = (end - start) / 4;
    int r = start;

    float4 A0, A1, A2, A3;
    if (nIter > 0) {
        A0 = __ldcs(ref4 + (size_t)(r + 0) * (N_PC / 4) + lane);
        A1 = __ldcs(ref4 + (size_t)(r + 1) * (N_PC / 4) + lane);
        A2 = __ldcs(ref4 + (size_t)(r + 2) * (N_PC / 4) + lane);
        A3 = __ldcs(ref4 + (size_t)(r + 3) * (N_PC / 4) + lane);
    }

    for (int it = 0; it < nIter; it++) {
        float4 B0, B1, B2, B3;
        if (it + 1 < nIter) {
            int rn = r + 4;
            B0 = __ldcs(ref4 + (size_t)(rn + 0) * (N_PC / 4) + lane);
            B1 = __ldcs(ref4 + (size_t)(rn + 1) * (N_PC / 4) + lane);
            B2 = __ldcs(ref4 + (size_t)(rn + 2) * (N_PC / 4) + lane);
            B3 = __ldcs(ref4 + (size_t)(rn + 3) * (N_PC / 4) + lane);
        }

        float s0 = fabsf(A0.x - q.x) + fabsf(A0.y - q.y) + fabsf(A0.z - q.z) + fabsf(A0.w - q.w);
        float s1 = fabsf(A1.x - q.x) + fabsf(A1.y - q.y) + fabsf(A1.z - q.z) + fabsf(A1.w - q.w);
        float s2 = fabsf(A2.x - q.x) + fabsf(A2.y - q.y) + fabsf(A2.z - q.z) + fabsf(A2.w - q.w);
        float s3 = fabsf(A3.x - q.x) + fabsf(A3.y - q.y) + fabsf(A3.z - q.z) + fabsf(A3.w - q.w);

        #pragma unroll
        for (int off = 16; off > 0; off >>= 1) {
            s0 += __shfl_xor_sync(0xFFFFFFFFu, s0, off);
            s1 += __shfl_xor_sync(0xFFFFFFFFu, s1, off);
            s2 += __shfl_xor_sync(0xFFFFFFFFu, s2, off);
            s3 += __shfl_xor_sync(0xFFFFFFFFu, s3, off);
        }

        if (lane == 0) {
            if (s0 < kmax) { bubble_insert(topd, topi, s0, r + 0); kmax = topd[TOP_K - 1]; }
            if (s1 < kmax) { bubble_insert(topd, topi, s1, r + 1); kmax = topd[TOP_K - 1]; }
            if (s2 < kmax) { bubble_insert(topd, topi, s2, r + 2); kmax = topd[TOP_K - 1]; }
            if (s3 < kmax) { bubble_insert(topd, topi, s3, r + 3); kmax = topd[TOP_K - 1]; }
        }

        A0 = B0; A1 = B1; A2 = B2; A3 = B3;
        r += 4;
    }
    for (; r < end; r++) {
        float4 a0 = __ldcs(ref4 + (size_t)r * (N_PC / 4) + lane);
        float s0 = fabsf(a0.x - q.x) + fabsf(a0.y - q.y) + fabsf(a0.z - q.z) + fabsf(a0.w - q.w);
        #pragma unroll
        for (int off = 16; off > 0; off >>= 1)
            s0 += __shfl_xor_sync(0xFFFFFFFFu, s0, off);
        if (lane == 0 && s0 < kmax) {
            bubble_insert(topd, topi, s0, r);
            kmax = topd[TOP_K - 1];
        }
    }

    __shared__ float sbd[WARPS_PER_BLOCK * TOP_K];   // 128
    __shared__ int   sbi[WARPS_PER_BLOCK * TOP_K];
    if (lane == 0) {
        #pragma unroll
        for (int t = 0; t < TOP_K; t++) {
            sbd[wid * TOP_K + t] = topd[t];
            sbi[wid * TOP_K + t] = topi[t];
        }
    }
    __syncthreads();

    if (tid < 128) {
        float v  = sbd[tid];
        int   id = sbi[tid];
        int rank = 0;
        #pragma unroll 8
        for (int j = 0; j < 128; j++) {
            float o = sbd[j];
            rank += (o < v) || (o == v && j < tid);
        }
        if (rank < TOP_K) {
            g_cand_d[blockIdx.x * TOP_K + rank] = v;   // sorted by rank
            g_cand_i[blockIdx.x * TOP_K + rank] = id;
        }
    }
}

// ---------------------------------------------------------------------------
// Kernel C (single merge): 1 block x 1024 threads.
// Phase 1: tau = 16th smallest of the 592 per-block MINIMA.
//   Correct: the 16 block-minima <= tau are 16 distinct candidates, so the
//   global 16th-smallest <= tau; every candidate needed survives the filter.
//   Tight (distribution-free): #rows <= tau ~= 16 + O(block collisions).
//   Computed via 19-warp bitonic keep-16 (304) -> rank-select the 16th.
// Phase 2: coalesced scan of 9472 candidates; survivors (d <= tau) appended
//   to shared (expected ~16-40; cap 2048 with astronomically small overflow).
// Phase 3: rank-select top-16 among survivors (tie-break on candidate slot ->
//   deterministic regardless of atomic order); gather psuedo; mean.
// ---------------------------------------------------------------------------
__global__ void __launch_bounds__(MERGE_T)
merge_kernel(const float* __restrict__ psuedo,
             float* __restrict__ out) {
    const int tid  = threadIdx.x;
    const int lane = tid & 31;
    const int wid  = tid >> 5;

    __shared__ float s_m2[MIN_KEEP];   // 304 warp-filtered minima
    __shared__ float s_tau;
    __shared__ int   s_cnt;
    __shared__ float s_d[SURV_CAP];
    __shared__ int   s_c[SURV_CAP];    // candidate slot (tie-break key)
    __shared__ float s_sel[TOP_K];

    if (tid == 0) s_cnt = 0;

    // ---- Phase 1a: per-warp bitonic keep-16 of block minima ----
    if (tid < MIN_PAD) {               // 19 full warps
        float v = (tid < BLOCKS) ? g_cand_d[tid * TOP_K] : FLT_MAX;  // rank-0 = block min
        bitonic32v(v, lane);
        if (lane < TOP_K) s_m2[wid * TOP_K + lane] = v;
    }
    __syncthreads();

    // ---- Phase 1b: rank-select the 16th smallest of 304 ----
    if (tid < MIN_KEEP) {
        float v = s_m2[tid];
        int rank = 0;
        #pragma unroll 8
        for (int j = 0; j < MIN_KEEP; j++) {
            float o = s_m2[j];
            rank += (o < v) || (o == v && j < tid);
        }
        if (rank == TOP_K - 1) s_tau = v;
    }
    __syncthreads();
    const float tau = s_tau;

    // ---- Phase 2: coalesced scan + threshold filter ----
    {
        const int ROUNDS = (N_CAND + MERGE_T - 1) / MERGE_T;   // 10
        float vb[ROUNDS];
        #pragma unroll
        for (int t = 0; t < ROUNDS; t++) {
            int c = tid + t * MERGE_T;
            vb[t] = (c < N_CAND) ? g_cand_d[c] : FLT_MAX;
        }
        #pragma unroll
        for (int t = 0; t < ROUNDS; t++) {
            int c = tid + t * MERGE_T;
            if (vb[t] <= tau) {
                int pos = atomicAdd(&s_cnt, 1);
                if (pos < SURV_CAP) {
                    s_d[pos] = vb[t];
                    s_c[pos] = c;
                }
            }
        }
    }
    __syncthreads();
    const int cnt = (s_cnt < SURV_CAP) ? s_cnt : SURV_CAP;

    // ---- Phase 3: rank-select top-16 of survivors, gather, mean ----
    if (tid < cnt) {
        float v = s_d[tid];
        int   c = s_c[tid];
        int rank = 0;
        for (int j = 0; j < cnt; j++) {
            float o = s_d[j];
            rank += (o < v) || (o == v && s_c[j] < c);
        }
        if (rank < TOP_K) s_sel[rank] = psuedo[g_cand_i[c]];
    }
    __syncthreads();

    if (tid < 32) {
        float v = (tid < TOP_K) ? s_sel[tid] : 0.0f;
        #pragma unroll
        for (int off = 16; off > 0; off >>= 1)
            v += __shfl_xor_sync(0xFFFFFFFFu, v, off);
        if (tid == 0) out[0] = v * (1.0f / TOP_K);
    }
}

// ---------------------------------------------------------------------------
// Launch (4 kernels)
// ---------------------------------------------------------------------------
extern "C" void kernel_launch(void* const* d_in, const int* in_sizes, int n_in,
                              void* d_out, int out_size) {
    const float* data_in = (const float*)d_in[0];
    const float* tmat    = (const float*)d_in[1];
    const float* ref     = (const float*)d_in[2];
    const float* psuedo  = (const float*)d_in[3];
    float* out = (float*)d_out;

    project_partial<<<PROJ_BLOCKS, N_PC>>>(data_in, tmat);
    project_reduce<<<1, N_PC>>>();
    dist_topk_kernel<<<BLOCKS, THREADS>>>(ref);
    merge_kernel<<<1, MERGE_T>>>(psuedo, out);
}

// round 11
// speedup vs baseline: 2.3008x; 1.2000x over previous
#include <cuda_runtime.h>
#include <float.h>

#define N_REF   500000
#define N_PC    128
#define N_FEAT  2000
#define TOP_K   16

#define BLOCKS           592
#define THREADS          256
#define WARPS_PER_BLOCK  (THREADS / 32)
#define TOTAL_WARPS      (BLOCKS * WARPS_PER_BLOCK)   // 4736
#define N_CAND           (BLOCKS * TOP_K)             // 9472

#define PROJ_BLOCKS      50
#define FEAT_PER_BLOCK   (N_FEAT / PROJ_BLOCKS)       // 40

#define MERGE_T          1024
#define SURV_CAP         2048
#define MIN_PAD          608                          // 19 warps * 32
#define MIN_KEEP         304                          // 19 * 16

// Scratch (no cudaMalloc allowed)
__device__ float g_qpart[PROJ_BLOCKS * N_PC];
__device__ float g_query[N_PC];
__device__ float g_cand_d[N_CAND];
__device__ int   g_cand_i[N_CAND];

// ---------------------------------------------------------------------------
// Warp-distributed top-16 insert. Lane l (<16) holds the l-th smallest
// (dval, divx); lanes >=16 hold garbage (init FLT_MAX) and are never read.
// v must be warp-uniform (it is: butterfly reduction leaves the sum in all
// lanes). ~7 instructions, no serial dependency chain.
// ---------------------------------------------------------------------------
__device__ __forceinline__ void warp_insert16(float& dval, int& divx,
                                              float& kmax, int lane,
                                              float v, int id) {
    unsigned m = __ballot_sync(0xFFFFFFFFu, dval < v);
    int pos = __popc(m & 0xFFFFu);          // insertion slot among lanes 0..15
    float up_d = __shfl_up_sync(0xFFFFFFFFu, dval, 1);
    int   up_i = __shfl_up_sync(0xFFFFFFFFu, divx, 1);
    if (lane >= pos) {
        dval = (lane == pos) ? v  : up_d;
        divx = (lane == pos) ? id : up_i;
    }
    kmax = __shfl_sync(0xFFFFFFFFu, dval, 15);
}

// ---------------------------------------------------------------------------
// Warp bitonic sort of 32 floats (ascending by lane), values only.
// ---------------------------------------------------------------------------
__device__ __forceinline__ void bitonic32v(float& v, int lane) {
    #pragma unroll
    for (int k = 2; k <= 32; k <<= 1) {
        #pragma unroll
        for (int j = k >> 1; j > 0; j >>= 1) {
            float ov = __shfl_xor_sync(0xFFFFFFFFu, v, j);
            bool up      = ((lane & k) == 0);
            bool lower   = ((lane & j) == 0);
            bool takeMin = (lower == up);
            bool sel = takeMin ? (ov < v) : (ov > v);
            v = sel ? ov : v;
        }
    }
}

// ---------------------------------------------------------------------------
// Kernel A1/A2: query projection (split 50 ways, then reduce)
// ---------------------------------------------------------------------------
__global__ void project_partial(const float* __restrict__ data_in,
                                const float* __restrict__ tmat) {
    int j  = threadIdx.x;
    int b  = blockIdx.x;
    int k0 = b * FEAT_PER_BLOCK;
    float acc = 0.0f;
    #pragma unroll 8
    for (int k = k0; k < k0 + FEAT_PER_BLOCK; k++)
        acc += data_in[k] * tmat[k * N_PC + j];
    g_qpart[b * N_PC + j] = acc;
}

__global__ void project_reduce() {
    int j = threadIdx.x;
    float acc = 0.0f;
    #pragma unroll
    for (int b = 0; b < PROJ_BLOCKS; b++) acc += g_qpart[b * N_PC + j];
    g_query[j] = acc;
}

// ---------------------------------------------------------------------------
// Kernel B: streaming L1 distance, warp/row, 4-row unroll + register
// double-buffer prefetch (R8). NEW: warp-distributed top-16 (no lane-0
// serial insert chains, ~30 fewer registers). Tail: parallel rank-select.
// Rank order in g_cand is ascending; rank 0 = block min (merge depends on it).
// ---------------------------------------------------------------------------
__global__ void __launch_bounds__(THREADS)
dist_topk_kernel(const float* __restrict__ ref) {
    const int tid  = threadIdx.x;
    const int lane = tid & 31;
    const int wid  = tid >> 5;
    const int gw   = blockIdx.x * WARPS_PER_BLOCK + wid;

    const float4 q = reinterpret_cast<const float4*>(g_query)[lane];

    const int chunk = (N_REF + TOTAL_WARPS - 1) / TOTAL_WARPS;  // 106
    int start = gw * chunk;
    int end   = start + chunk;
    if (start > N_REF) start = N_REF;
    if (end   > N_REF) end   = N_REF;

    // distributed top-16 state
    float dval = FLT_MAX;
    int   divx = 0;
    float kmax = FLT_MAX;

    const float4* __restrict__ ref4 = reinterpret_cast<const float4*>(ref);

    const int nIter = (end - start) / 4;
    int r = start;

    float4 A0, A1, A2, A3;
    if (nIter > 0) {
        A0 = __ldcs(ref4 + (size_t)(r + 0) * (N_PC / 4) + lane);
        A1 = __ldcs(ref4 + (size_t)(r + 1) * (N_PC / 4) + lane);
        A2 = __ldcs(ref4 + (size_t)(r + 2) * (N_PC / 4) + lane);
        A3 = __ldcs(ref4 + (size_t)(r + 3) * (N_PC / 4) + lane);
    }

    for (int it = 0; it < nIter; it++) {
        float4 B0, B1, B2, B3;
        if (it + 1 < nIter) {
            int rn = r + 4;
            B0 = __ldcs(ref4 + (size_t)(rn + 0) * (N_PC / 4) + lane);
            B1 = __ldcs(ref4 + (size_t)(rn + 1) * (N_PC / 4) + lane);
            B2 = __ldcs(ref4 + (size_t)(rn + 2) * (N_PC / 4) + lane);
            B3 = __ldcs(ref4 + (size_t)(rn + 3) * (N_PC / 4) + lane);
        }

        float s0 = fabsf(A0.x - q.x) + fabsf(A0.y - q.y) + fabsf(A0.z - q.z) + fabsf(A0.w - q.w);
        float s1 = fabsf(A1.x - q.x) + fabsf(A1.y - q.y) + fabsf(A1.z - q.z) + fabsf(A1.w - q.w);
        float s2 = fabsf(A2.x - q.x) + fabsf(A2.y - q.y) + fabsf(A2.z - q.z) + fabsf(A2.w - q.w);
        float s3 = fabsf(A3.x - q.x) + fabsf(A3.y - q.y) + fabsf(A3.z - q.z) + fabsf(A3.w - q.w);

        #pragma unroll
        for (int off = 16; off > 0; off >>= 1) {
            s0 += __shfl_xor_sync(0xFFFFFFFFu, s0, off);
            s1 += __shfl_xor_sync(0xFFFFFFFFu, s1, off);
            s2 += __shfl_xor_sync(0xFFFFFFFFu, s2, off);
            s3 += __shfl_xor_sync(0xFFFFFFFFu, s3, off);
        }
        // butterfly leaves sums in ALL lanes -> warp-uniform inserts
        if (s0 < kmax) warp_insert16(dval, divx, kmax, lane, s0, r + 0);
        if (s1 < kmax) warp_insert16(dval, divx, kmax, lane, s1, r + 1);
        if (s2 < kmax) warp_insert16(dval, divx, kmax, lane, s2, r + 2);
        if (s3 < kmax) warp_insert16(dval, divx, kmax, lane, s3, r + 3);

        A0 = B0; A1 = B1; A2 = B2; A3 = B3;
        r += 4;
    }
    for (; r < end; r++) {
        float4 a0 = __ldcs(ref4 + (size_t)r * (N_PC / 4) + lane);
        float s0 = fabsf(a0.x - q.x) + fabsf(a0.y - q.y) + fabsf(a0.z - q.z) + fabsf(a0.w - q.w);
        #pragma unroll
        for (int off = 16; off > 0; off >>= 1)
            s0 += __shfl_xor_sync(0xFFFFFFFFu, s0, off);
        if (s0 < kmax) warp_insert16(dval, divx, kmax, lane, s0, r);
    }

    // ---- tail: parallel rank-select block top-16 over 128 shared entries ----
    __shared__ float sbd[WARPS_PER_BLOCK * TOP_K];   // 128
    __shared__ int   sbi[WARPS_PER_BLOCK * TOP_K];
    if (lane < TOP_K) {
        sbd[wid * TOP_K + lane] = dval;
        sbi[wid * TOP_K + lane] = divx;
    }
    __syncthreads();

    if (tid < 128) {
        float v  = sbd[tid];
        int   id = sbi[tid];
        int rank = 0;
        #pragma unroll 8
        for (int j = 0; j < 128; j++) {
            float o = sbd[j];
            rank += (o < v) || (o == v && j < tid);
        }
        if (rank < TOP_K) {
            g_cand_d[blockIdx.x * TOP_K + rank] = v;   // sorted by rank
            g_cand_i[blockIdx.x * TOP_K + rank] = id;
        }
    }
}

// ---------------------------------------------------------------------------
// Kernel C (single merge, UNCHANGED from R10): 1 block x 1024 threads.
// tau = 16th smallest of the 592 per-block minima (provably >= global 16th;
// distribution-free survivor count ~16-40). Filter, rank-select, gather, mean.
// ---------------------------------------------------------------------------
__global__ void __launch_bounds__(MERGE_T)
merge_kernel(const float* __restrict__ psuedo,
             float* __restrict__ out) {
    const int tid  = threadIdx.x;
    const int lane = tid & 31;
    const int wid  = tid >> 5;

    __shared__ float s_m2[MIN_KEEP];   // 304 warp-filtered minima
    __shared__ float s_tau;
    __shared__ int   s_cnt;
    __shared__ float s_d[SURV_CAP];
    __shared__ int   s_c[SURV_CAP];    // candidate slot (tie-break key)
    __shared__ float s_sel[TOP_K];

    if (tid == 0) s_cnt = 0;

    // ---- Phase 1a: per-warp bitonic keep-16 of block minima ----
    if (tid < MIN_PAD) {               // 19 full warps
        float v = (tid < BLOCKS) ? g_cand_d[tid * TOP_K] : FLT_MAX;  // rank-0 = block min
        bitonic32v(v, lane);
        if (lane < TOP_K) s_m2[wid * TOP_K + lane] = v;
    }
    __syncthreads();

    // ---- Phase 1b: rank-select the 16th smallest of 304 ----
    if (tid < MIN_KEEP) {
        float v = s_m2[tid];
        int rank = 0;
        #pragma unroll 8
        for (int j = 0; j < MIN_KEEP; j++) {
            float o = s_m2[j];
            rank += (o < v) || (o == v && j < tid);
        }
        if (rank == TOP_K - 1) s_tau = v;
    }
    __syncthreads();
    const float tau = s_tau;

    // ---- Phase 2: coalesced scan + threshold filter ----
    {
        const int ROUNDS = (N_CAND + MERGE_T - 1) / MERGE_T;   // 10
        float vb[ROUNDS];
        #pragma unroll
        for (int t = 0; t < ROUNDS; t++) {
            int c = tid + t * MERGE_T;
            vb[t] = (c < N_CAND) ? g_cand_d[c] : FLT_MAX;
        }
        #pragma unroll
        for (int t = 0; t < ROUNDS; t++) {
            int c = tid + t * MERGE_T;
            if (vb[t] <= tau) {
                int pos = atomicAdd(&s_cnt, 1);
                if (pos < SURV_CAP) {
                    s_d[pos] = vb[t];
                    s_c[pos] = c;
                }
            }
        }
    }
    __syncthreads();
    const int cnt = (s_cnt < SURV_CAP) ? s_cnt : SURV_CAP;

    // ---- Phase 3: rank-select top-16 of survivors, gather, mean ----
    if (tid < cnt) {
        float v = s_d[tid];
        int   c = s_c[tid];
        int rank = 0;
        for (int j = 0; j < cnt; j++) {
            float o = s_d[j];
            rank += (o < v) || (o == v && s_c[j] < c);
        }
        if (rank < TOP_K) s_sel[rank] = psuedo[g_cand_i[c]];
    }
    __syncthreads();

    if (tid < 32) {
        float v = (tid < TOP_K) ? s_sel[tid] : 0.0f;
        #pragma unroll
        for (int off = 16; off > 0; off >>= 1)
            v += __shfl_xor_sync(0xFFFFFFFFu, v, off);
        if (tid == 0) out[0] = v * (1.0f / TOP_K);
    }
}

// ---------------------------------------------------------------------------
// Launch (4 kernels)
// ---------------------------------------------------------------------------
extern "C" void kernel_launch(void* const* d_in, const int* in_sizes, int n_in,
                              void* d_out, int out_size) {
    const float* data_in = (const float*)d_in[0];
    const float* tmat    = (const float*)d_in[1];
    const float* ref     = (const float*)d_in[2];
    const float* psuedo  = (const float*)d_in[3];
    float* out = (float*)d_out;

    project_partial<<<PROJ_BLOCKS, N_PC>>>(data_in, tmat);
    project_reduce<<<1, N_PC>>>();
    dist_topk_kernel<<<BLOCKS, THREADS>>>(ref);
    merge_kernel<<<1, MERGE_T>>>(psuedo, out);
}

// round 12
// speedup vs baseline: 2.3945x; 1.0407x over previous
#include <cuda_runtime.h>
#include <float.h>

#define N_REF   500000
#define N_PC    128
#define N_FEAT  2000
#define TOP_K   16

#define BLOCKS           592
#define THREADS          256
#define WARPS_PER_BLOCK  (THREADS / 32)
#define TOTAL_WARPS      (BLOCKS * WARPS_PER_BLOCK)   // 4736
#define N_CAND           (BLOCKS * TOP_K)             // 9472

#define PROJ_BLOCKS      50
#define FEAT_PER_BLOCK   (N_FEAT / PROJ_BLOCKS)       // 40

#define MERGE_T          1024
#define MERGE_ROUNDS     ((N_CAND + MERGE_T - 1) / MERGE_T)   // 10
#define SURV_CAP         2048
#define MIN_PAD          608                          // 19 warps * 32
#define MIN_KEEP         304                          // 19 * 16

// Scratch (no cudaMalloc allowed)
__device__ float g_qpart[PROJ_BLOCKS * N_PC];
__device__ float g_query[N_PC];
__device__ float g_cand_d[N_CAND];
__device__ int   g_cand_i[N_CAND];

// ---------------------------------------------------------------------------
// Warp-distributed top-16 insert. Lane l (<16) holds the l-th smallest
// (dval, divx). v must be warp-uniform. ~7 instructions, no serial chain.
// ---------------------------------------------------------------------------
__device__ __forceinline__ void warp_insert16(float& dval, int& divx,
                                              float& kmax, int lane,
                                              float v, int id) {
    unsigned m = __ballot_sync(0xFFFFFFFFu, dval < v);
    int pos = __popc(m & 0xFFFFu);
    float up_d = __shfl_up_sync(0xFFFFFFFFu, dval, 1);
    int   up_i = __shfl_up_sync(0xFFFFFFFFu, divx, 1);
    if (lane >= pos) {
        dval = (lane == pos) ? v  : up_d;
        divx = (lane == pos) ? id : up_i;
    }
    kmax = __shfl_sync(0xFFFFFFFFu, dval, 15);
}

// ---------------------------------------------------------------------------
// Warp bitonic sort of 32 floats (ascending by lane), values only.
// ---------------------------------------------------------------------------
__device__ __forceinline__ void bitonic32v(float& v, int lane) {
    #pragma unroll
    for (int k = 2; k <= 32; k <<= 1) {
        #pragma unroll
        for (int j = k >> 1; j > 0; j >>= 1) {
            float ov = __shfl_xor_sync(0xFFFFFFFFu, v, j);
            bool up      = ((lane & k) == 0);
            bool lower   = ((lane & j) == 0);
            bool takeMin = (lower == up);
            bool sel = takeMin ? (ov < v) : (ov > v);
            v = sel ? ov : v;
        }
    }
}

// ---------------------------------------------------------------------------
// Kernel A1/A2: query projection (split 50 ways, then reduce)
// ---------------------------------------------------------------------------
__global__ void project_partial(const float* __restrict__ data_in,
                                const float* __restrict__ tmat) {
    int j  = threadIdx.x;
    int b  = blockIdx.x;
    int k0 = b * FEAT_PER_BLOCK;
    float acc = 0.0f;
    #pragma unroll 8
    for (int k = k0; k < k0 + FEAT_PER_BLOCK; k++)
        acc += data_in[k] * tmat[k * N_PC + j];
    g_qpart[b * N_PC + j] = acc;
}

__global__ void project_reduce() {
    int j = threadIdx.x;
    float acc = 0.0f;
    #pragma unroll
    for (int b = 0; b < PROJ_BLOCKS; b++) acc += g_qpart[b * N_PC + j];
    g_query[j] = acc;
}

// ---------------------------------------------------------------------------
// Kernel B (UNCHANGED from R11 best): streaming L1 distance, warp/row,
// 4-row unroll + register double-buffer prefetch, warp-distributed top-16,
// parallel rank-select tail. g_cand rows sorted ascending; rank 0 = block min.
// ---------------------------------------------------------------------------
__global__ void __launch_bounds__(THREADS)
dist_topk_kernel(const float* __restrict__ ref) {
    const int tid  = threadIdx.x;
    const int lane = tid & 31;
    const int wid  = tid >> 5;
    const int gw   = blockIdx.x * WARPS_PER_BLOCK + wid;

    const float4 q = reinterpret_cast<const float4*>(g_query)[lane];

    const int chunk = (N_REF + TOTAL_WARPS - 1) / TOTAL_WARPS;  // 106
    int start = gw * chunk;
    int end   = start + chunk;
    if (start > N_REF) start = N_REF;
    if (end   > N_REF) end   = N_REF;

    float dval = FLT_MAX;
    int   divx = 0;
    float kmax = FLT_MAX;

    const float4* __restrict__ ref4 = reinterpret_cast<const float4*>(ref);

    const int nIter = (end - start) / 4;
    int r = start;

    float4 A0, A1, A2, A3;
    if (nIter > 0) {
        A0 = __ldcs(ref4 + (size_t)(r + 0) * (N_PC / 4) + lane);
        A1 = __ldcs(ref4 + (size_t)(r + 1) * (N_PC / 4) + lane);
        A2 = __ldcs(ref4 + (size_t)(r + 2) * (N_PC / 4) + lane);
        A3 = __ldcs(ref4 + (size_t)(r + 3) * (N_PC / 4) + lane);
    }

    for (int it = 0; it < nIter; it++) {
        float4 B0, B1, B2, B3;
        if (it + 1 < nIter) {
            int rn = r + 4;
            B0 = __ldcs(ref4 + (size_t)(rn + 0) * (N_PC / 4) + lane);
            B1 = __ldcs(ref4 + (size_t)(rn + 1) * (N_PC / 4) + lane);
            B2 = __ldcs(ref4 + (size_t)(rn + 2) * (N_PC / 4) + lane);
            B3 = __ldcs(ref4 + (size_t)(rn + 3) * (N_PC / 4) + lane);
        }

        float s0 = fabsf(A0.x - q.x) + fabsf(A0.y - q.y) + fabsf(A0.z - q.z) + fabsf(A0.w - q.w);
        float s1 = fabsf(A1.x - q.x) + fabsf(A1.y - q.y) + fabsf(A1.z - q.z) + fabsf(A1.w - q.w);
        float s2 = fabsf(A2.x - q.x) + fabsf(A2.y - q.y) + fabsf(A2.z - q.z) + fabsf(A2.w - q.w);
        float s3 = fabsf(A3.x - q.x) + fabsf(A3.y - q.y) + fabsf(A3.z - q.z) + fabsf(A3.w - q.w);

        #pragma unroll
        for (int off = 16; off > 0; off >>= 1) {
            s0 += __shfl_xor_sync(0xFFFFFFFFu, s0, off);
            s1 += __shfl_xor_sync(0xFFFFFFFFu, s1, off);
            s2 += __shfl_xor_sync(0xFFFFFFFFu, s2, off);
            s3 += __shfl_xor_sync(0xFFFFFFFFu, s3, off);
        }
        if (s0 < kmax) warp_insert16(dval, divx, kmax, lane, s0, r + 0);
        if (s1 < kmax) warp_insert16(dval, divx, kmax, lane, s1, r + 1);
        if (s2 < kmax) warp_insert16(dval, divx, kmax, lane, s2, r + 2);
        if (s3 < kmax) warp_insert16(dval, divx, kmax, lane, s3, r + 3);

        A0 = B0; A1 = B1; A2 = B2; A3 = B3;
        r += 4;
    }
    for (; r < end; r++) {
        float4 a0 = __ldcs(ref4 + (size_t)r * (N_PC / 4) + lane);
        float s0 = fabsf(a0.x - q.x) + fabsf(a0.y - q.y) + fabsf(a0.z - q.z) + fabsf(a0.w - q.w);
        #pragma unroll
        for (int off = 16; off > 0; off >>= 1)
            s0 += __shfl_xor_sync(0xFFFFFFFFu, s0, off);
        if (s0 < kmax) warp_insert16(dval, divx, kmax, lane, s0, r);
    }

    __shared__ float sbd[WARPS_PER_BLOCK * TOP_K];   // 128
    __shared__ int   sbi[WARPS_PER_BLOCK * TOP_K];
    if (lane < TOP_K) {
        sbd[wid * TOP_K + lane] = dval;
        sbi[wid * TOP_K + lane] = divx;
    }
    __syncthreads();

    if (tid < 128) {
        float v  = sbd[tid];
        int   id = sbi[tid];
        int rank = 0;
        #pragma unroll 8
        for (int j = 0; j < 128; j++) {
            float o = sbd[j];
            rank += (o < v) || (o == v && j < tid);
        }
        if (rank < TOP_K) {
            g_cand_d[blockIdx.x * TOP_K + rank] = v;   // sorted by rank
            g_cand_i[blockIdx.x * TOP_K + rank] = id;
        }
    }
}

// ---------------------------------------------------------------------------
// Kernel C (merge, RESTRUCTURED): 1 block x 1024 threads.
//  - All global loads issued at entry (candidate batch + block minima) so L2
//    latency overlaps the tau computation instead of following it.
//  - tau = 16th smallest of the 592 per-block minima (provable upper bound on
//    the global 16th-smallest; survivor count ~16-40, distribution-free).
//  - Warp-aggregated survivor append (1 atomic/warp/round).
//  - Final rank-select among survivors with candidate-slot tie-break
//    (deterministic regardless of append order); gather psuedo; mean.
// ---------------------------------------------------------------------------
__global__ void __launch_bounds__(MERGE_T)
merge_kernel(const float* __restrict__ psuedo,
             float* __restrict__ out) {
    const int tid  = threadIdx.x;
    const int lane = tid & 31;
    const int wid  = tid >> 5;

    __shared__ float s_m2[MIN_KEEP];   // 304 warp-filtered minima
    __shared__ float s_tau;
    __shared__ int   s_cnt;
    __shared__ float s_d[SURV_CAP];
    __shared__ int   s_c[SURV_CAP];
    __shared__ float s_sel[TOP_K];

    if (tid == 0) s_cnt = 0;

    // ---- issue ALL global loads up front (overlap with phase 1 compute) ----
    float vb[MERGE_ROUNDS];
    #pragma unroll
    for (int t = 0; t < MERGE_ROUNDS; t++) {
        int c = tid + t * MERGE_T;
        vb[t] = (c < N_CAND) ? g_cand_d[c] : FLT_MAX;
    }
    float vmin = FLT_MAX;
    if (tid < BLOCKS) vmin = g_cand_d[tid * TOP_K];    // rank-0 = block min

    // ---- phase 1: tau = 16th smallest of 592 block minima ----
    if (tid < MIN_PAD) {               // 19 full warps
        bitonic32v(vmin, lane);
        if (lane < TOP_K) s_m2[wid * TOP_K + lane] = vmin;
    }
    __syncthreads();

    if (tid < MIN_KEEP) {
        float v = s_m2[tid];
        int rank = 0;
        #pragma unroll 8
        for (int j = 0; j < MIN_KEEP; j++) {
            float o = s_m2[j];
            rank += (o < v) || (o == v && j < tid);
        }
        if (rank == TOP_K - 1) s_tau = v;
    }
    __syncthreads();
    const float tau = s_tau;

    // ---- phase 2: threshold filter with warp-aggregated append ----
    #pragma unroll
    for (int t = 0; t < MERGE_ROUNDS; t++) {
        int c = tid + t * MERGE_T;
        bool pred = (vb[t] <= tau);
        unsigned m = __ballot_sync(0xFFFFFFFFu, pred);
        if (m) {
            int base = 0;
            if (lane == 0) base = atomicAdd(&s_cnt, __popc(m));
            base = __shfl_sync(0xFFFFFFFFu, base, 0);
            if (pred) {
                int pos = base + __popc(m & ((1u << lane) - 1u));
                if (pos < SURV_CAP) {
                    s_d[pos] = vb[t];
                    s_c[pos] = c;
                }
            }
        }
    }
    __syncthreads();
    const int cnt = (s_cnt < SURV_CAP) ? s_cnt : SURV_CAP;

    // ---- phase 3: rank-select top-16 of survivors, gather, mean ----
    if (tid < cnt) {
        float v = s_d[tid];
        int   c = s_c[tid];
        int rank = 0;
        for (int j = 0; j < cnt; j++) {
            float o = s_d[j];
            rank += (o < v) || (o == v && s_c[j] < c);
        }
        if (rank < TOP_K) s_sel[rank] = psuedo[g_cand_i[c]];
    }
    __syncthreads();

    if (tid < 32) {
        float v = (tid < TOP_K) ? s_sel[tid] : 0.0f;
        #pragma unroll
        for (int off = 16; off > 0; off >>= 1)
            v += __shfl_xor_sync(0xFFFFFFFFu, v, off);
        if (tid == 0) out[0] = v * (1.0f / TOP_K);
    }
}

// ---------------------------------------------------------------------------
// Launch (4 kernels)
// ---------------------------------------------------------------------------
extern "C" void kernel_launch(void* const* d_in, const int* in_sizes, int n_in,
                              void* d_out, int out_size) {
    const float* data_in = (const float*)d_in[0];
    const float* tmat    = (const float*)d_in[1];
    const float* ref     = (const float*)d_in[2];
    const float* psuedo  = (const float*)d_in[3];
    float* out = (float*)d_out;

    project_partial<<<PROJ_BLOCKS, N_PC>>>(data_in, tmat);
    project_reduce<<<1, N_PC>>>();
    dist_topk_kernel<<<BLOCKS, THREADS>>>(ref);
    merge_kernel<<<1, MERGE_T>>>(psuedo, out);
}

// round 13
// speedup vs baseline: 2.5066x; 1.0468x over previous
#include <cuda_runtime.h>
#include <float.h>

#define N_REF   500000
#define N_PC    128
#define N_FEAT  2000
#define TOP_K   16

#define BLOCKS           592
#define THREADS          256
#define WARPS_PER_BLOCK  (THREADS / 32)
#define TOTAL_WARPS      (BLOCKS * WARPS_PER_BLOCK)   // 4736
#define N_CAND           (BLOCKS * TOP_K)             // 9472

#define PROJ_BLOCKS      50
#define FEAT_PER_BLOCK   (N_FEAT / PROJ_BLOCKS)       // 40

#define MERGE_T          1024
#define MERGE_ROUNDS     ((N_CAND + MERGE_T - 1) / MERGE_T)   // 10
#define SURV_CAP         2048
#define MIN_PAD          608                          // 19 warps * 32
#define N_LISTS          19

// Scratch (no cudaMalloc allowed)
__device__ float g_qpart[PROJ_BLOCKS * N_PC];
__device__ float g_cand_d[N_CAND];
__device__ int   g_cand_i[N_CAND];
__device__ float g_bmin[BLOCKS];      // per-block minimum (compact, coalesced)

// ---------------------------------------------------------------------------
// Warp-distributed top-16 insert. Lane l (<16) holds the l-th smallest
// (dval, divx). v must be warp-uniform. ~7 instructions, no serial chain.
// ---------------------------------------------------------------------------
__device__ __forceinline__ void warp_insert16(float& dval, int& divx,
                                              float& kmax, int lane,
                                              float v, int id) {
    unsigned m = __ballot_sync(0xFFFFFFFFu, dval < v);
    int pos = __popc(m & 0xFFFFu);
    float up_d = __shfl_up_sync(0xFFFFFFFFu, dval, 1);
    int   up_i = __shfl_up_sync(0xFFFFFFFFu, divx, 1);
    if (lane >= pos) {
        dval = (lane == pos) ? v  : up_d;
        divx = (lane == pos) ? id : up_i;
    }
    kmax = __shfl_sync(0xFFFFFFFFu, dval, 15);
}

// ---------------------------------------------------------------------------
// Warp bitonic sort of 32 floats (ascending by lane), values only.
// ---------------------------------------------------------------------------
__device__ __forceinline__ void bitonic32v(float& v, int lane) {
    #pragma unroll
    for (int k = 2; k <= 32; k <<= 1) {
        #pragma unroll
        for (int j = k >> 1; j > 0; j >>= 1) {
            float ov = __shfl_xor_sync(0xFFFFFFFFu, v, j);
            bool up      = ((lane & k) == 0);
            bool lower   = ((lane & j) == 0);
            bool takeMin = (lower == up);
            bool sel = takeMin ? (ov < v) : (ov > v);
            v = sel ? ov : v;
        }
    }
}

// Bitonic MERGE of a 32-lane bitonic sequence -> ascending (5 stages).
__device__ __forceinline__ void bitonic_merge32(float& v, int lane) {
    #pragma unroll
    for (int j = 16; j > 0; j >>= 1) {
        float ov = __shfl_xor_sync(0xFFFFFFFFu, v, j);
        v = ((lane & j) == 0) ? fminf(v, ov) : fmaxf(v, ov);
    }
}

// ---------------------------------------------------------------------------
// Kernel A: partial query projection (block b covers 40 features).
// ---------------------------------------------------------------------------
__global__ void project_partial(const float* __restrict__ data_in,
                                const float* __restrict__ tmat) {
    int j  = threadIdx.x;
    int b  = blockIdx.x;
    int k0 = b * FEAT_PER_BLOCK;
    float acc = 0.0f;
    #pragma unroll 8
    for (int k = k0; k < k0 + FEAT_PER_BLOCK; k++)
        acc += data_in[k] * tmat[k * N_PC + j];
    g_qpart[b * N_PC + j] = acc;
}

// ---------------------------------------------------------------------------
// Kernel B: [prologue] reduce 50 projection partials -> shared (L2-hot, ~free)
//           [mainloop] BYTE-IDENTICAL to R11/R12 best: warp/row, 4-row unroll,
//             register double-buffer prefetch, warp-distributed top-16
//           [tail] parallel rank-select block top-16; also writes block min
//             to compact g_bmin for the merge kernel.
// ---------------------------------------------------------------------------
__global__ void __launch_bounds__(THREADS)
dist_topk_kernel(const float* __restrict__ ref) {
    const int tid  = threadIdx.x;
    const int lane = tid & 31;
    const int wid  = tid >> 5;
    const int gw   = blockIdx.x * WARPS_PER_BLOCK + wid;

    // ---- prologue: finish query projection into shared ----
    __shared__ __align__(16) float sq[N_PC];
    if (tid < N_PC) {
        float acc = 0.0f;
        #pragma unroll
        for (int b = 0; b < PROJ_BLOCKS; b++)
            acc += g_qpart[b * N_PC + tid];
        sq[tid] = acc;
    }
    __syncthreads();
    const float4 q = reinterpret_cast<const float4*>(sq)[lane];

    const int chunk = (N_REF + TOTAL_WARPS - 1) / TOTAL_WARPS;  // 106
    int start = gw * chunk;
    int end   = start + chunk;
    if (start > N_REF) start = N_REF;
    if (end   > N_REF) end   = N_REF;

    float dval = FLT_MAX;
    int   divx = 0;
    float kmax = FLT_MAX;

    const float4* __restrict__ ref4 = reinterpret_cast<const float4*>(ref);

    const int nIter = (end - start) / 4;
    int r = start;

    float4 A0, A1, A2, A3;
    if (nIter > 0) {
        A0 = __ldcs(ref4 + (size_t)(r + 0) * (N_PC / 4) + lane);
        A1 = __ldcs(ref4 + (size_t)(r + 1) * (N_PC / 4) + lane);
        A2 = __ldcs(ref4 + (size_t)(r + 2) * (N_PC / 4) + lane);
        A3 = __ldcs(ref4 + (size_t)(r + 3) * (N_PC / 4) + lane);
    }

    for (int it = 0; it < nIter; it++) {
        float4 B0, B1, B2, B3;
        if (it + 1 < nIter) {
            int rn = r + 4;
            B0 = __ldcs(ref4 + (size_t)(rn + 0) * (N_PC / 4) + lane);
            B1 = __ldcs(ref4 + (size_t)(rn + 1) * (N_PC / 4) + lane);
            B2 = __ldcs(ref4 + (size_t)(rn + 2) * (N_PC / 4) + lane);
            B3 = __ldcs(ref4 + (size_t)(rn + 3) * (N_PC / 4) + lane);
        }

        float s0 = fabsf(A0.x - q.x) + fabsf(A0.y - q.y) + fabsf(A0.z - q.z) + fabsf(A0.w - q.w);
        float s1 = fabsf(A1.x - q.x) + fabsf(A1.y - q.y) + fabsf(A1.z - q.z) + fabsf(A1.w - q.w);
        float s2 = fabsf(A2.x - q.x) + fabsf(A2.y - q.y) + fabsf(A2.z - q.z) + fabsf(A2.w - q.w);
        float s3 = fabsf(A3.x - q.x) + fabsf(A3.y - q.y) + fabsf(A3.z - q.z) + fabsf(A3.w - q.w);

        #pragma unroll
        for (int off = 16; off > 0; off >>= 1) {
            s0 += __shfl_xor_sync(0xFFFFFFFFu, s0, off);
            s1 += __shfl_xor_sync(0xFFFFFFFFu, s1, off);
            s2 += __shfl_xor_sync(0xFFFFFFFFu, s2, off);
            s3 += __shfl_xor_sync(0xFFFFFFFFu, s3, off);
        }
        if (s0 < kmax) warp_insert16(dval, divx, kmax, lane, s0, r + 0);
        if (s1 < kmax) warp_insert16(dval, divx, kmax, lane, s1, r + 1);
        if (s2 < kmax) warp_insert16(dval, divx, kmax, lane, s2, r + 2);
        if (s3 < kmax) warp_insert16(dval, divx, kmax, lane, s3, r + 3);

        A0 = B0; A1 = B1; A2 = B2; A3 = B3;
        r += 4;
    }
    for (; r < end; r++) {
        float4 a0 = __ldcs(ref4 + (size_t)r * (N_PC / 4) + lane);
        float s0 = fabsf(a0.x - q.x) + fabsf(a0.y - q.y) + fabsf(a0.z - q.z) + fabsf(a0.w - q.w);
        #pragma unroll
        for (int off = 16; off > 0; off >>= 1)
            s0 += __shfl_xor_sync(0xFFFFFFFFu, s0, off);
        if (s0 < kmax) warp_insert16(dval, divx, kmax, lane, s0, r);
    }

    __shared__ float sbd[WARPS_PER_BLOCK * TOP_K];   // 128
    __shared__ int   sbi[WARPS_PER_BLOCK * TOP_K];
    if (lane < TOP_K) {
        sbd[wid * TOP_K + lane] = dval;
        sbi[wid * TOP_K + lane] = divx;
    }
    __syncthreads();

    if (tid < 128) {
        float v  = sbd[tid];
        int   id = sbi[tid];
        int rank = 0;
        #pragma unroll 8
        for (int j = 0; j < 128; j++) {
            float o = sbd[j];
            rank += (o < v) || (o == v && j < tid);
        }
        if (rank < TOP_K) {
            g_cand_d[blockIdx.x * TOP_K + rank] = v;
            g_cand_i[blockIdx.x * TOP_K + rank] = id;
        }
        if (rank == 0) g_bmin[blockIdx.x] = v;   // compact block minimum
    }
}

// ---------------------------------------------------------------------------
// Kernel C (merge): 1 block x 1024 threads.
//  - All global loads issued at entry (candidate batch + COALESCED g_bmin).
//  - tau = EXACT 16th smallest of 592 block minima, via per-warp bitonic
//    keep-16 then a ping-pong bitonic merge tree over 19 sorted 16-lists
//    (19->10->5->3->2->1; exact sorting-network merges).
//  - Warp-aggregated survivor append; rank-select with slot tie-break
//    (deterministic); gather psuedo; mean.
// ---------------------------------------------------------------------------
__global__ void __launch_bounds__(MERGE_T)
merge_kernel(const float* __restrict__ psuedo,
             float* __restrict__ out) {
    const int tid  = threadIdx.x;
    const int lane = tid & 31;
    const int wid  = tid >> 5;

    __shared__ float s_a[N_LISTS * TOP_K];   // 304
    __shared__ float s_b[N_LISTS * TOP_K];
    __shared__ int   s_cnt;
    __shared__ float s_d[SURV_CAP];
    __shared__ int   s_c[SURV_CAP];
    __shared__ float s_sel[TOP_K];

    if (tid == 0) s_cnt = 0;

    // ---- issue ALL global loads up front ----
    float vb[MERGE_ROUNDS];
    #pragma unroll
    for (int t = 0; t < MERGE_ROUNDS; t++) {
        int c = tid + t * MERGE_T;
        vb[t] = (c < N_CAND) ? g_cand_d[c] : FLT_MAX;
    }
    float vmin = (tid < BLOCKS) ? g_bmin[tid] : FLT_MAX;   // coalesced

    // ---- phase 1a: per-warp bitonic sort-32, keep sorted 16 ----
    if (tid < MIN_PAD) {               // 19 full warps
        bitonic32v(vmin, lane);
        if (lane < TOP_K) s_a[wid * TOP_K + lane] = vmin;
    }
    __syncthreads();

    // ---- phase 1b: bitonic merge tree, 19 lists -> 1 (ping-pong) ----
    {
        float* src = s_a;
        float* dst = s_b;
        int n = N_LISTS;
        while (n > 1) {
            int half = n >> 1;
            if (wid < half) {
                // lanes 0-15: list 2w ascending; lanes 16-31: list 2w+1 reversed
                float v = (lane < TOP_K)
                        ? src[(2 * wid) * TOP_K + lane]
                        : src[(2 * wid + 1) * TOP_K + (31 - lane)];
                bitonic_merge32(v, lane);              // ascending sort of union
                if (lane < TOP_K) dst[wid * TOP_K + lane] = v;
            } else if ((n & 1) && wid == half) {
                if (lane < TOP_K)
                    dst[half * TOP_K + lane] = src[(n - 1) * TOP_K + lane];
            }
            __syncthreads();
            n = half + (n & 1);
            float* tmp = src; src = dst; dst = tmp;
        }
        // final sorted 16 sits in src[0..15]; tau = src[15]
        if (tid == 0) s_sel[0] = src[TOP_K - 1];   // stash tau
    }
    __syncthreads();
    const float tau = s_sel[0];

    // ---- phase 2: threshold filter with warp-aggregated append ----
    #pragma unroll
    for (int t = 0; t < MERGE_ROUNDS; t++) {
        int c = tid + t * MERGE_T;
        bool pred = (vb[t] <= tau);
        unsigned m = __ballot_sync(0xFFFFFFFFu, pred);
        if (m) {
            int base = 0;
            if (lane == 0) base = atomicAdd(&s_cnt, __popc(m));
            base = __shfl_sync(0xFFFFFFFFu, base, 0);
            if (pred) {
                int pos = base + __popc(m & ((1u << lane) - 1u));
                if (pos < SURV_CAP) {
                    s_d[pos] = vb[t];
                    s_c[pos] = c;
                }
            }
        }
    }
    __syncthreads();
    const int cnt = (s_cnt < SURV_CAP) ? s_cnt : SURV_CAP;

    // ---- phase 3: rank-select top-16 of survivors, gather, mean ----
    if (tid < cnt) {
        float v = s_d[tid];
        int   c = s_c[tid];
        int rank = 0;
        for (int j = 0; j < cnt; j++) {
            float o = s_d[j];
            rank += (o < v) || (o == v && s_c[j] < c);
        }
        if (rank < TOP_K) s_sel[rank] = psuedo[g_cand_i[c]];
    }
    __syncthreads();

    if (tid < 32) {
        float v = (tid < TOP_K) ? s_sel[tid] : 0.0f;
        #pragma unroll
        for (int off = 16; off > 0; off >>= 1)
            v += __shfl_xor_sync(0xFFFFFFFFu, v, off);
        if (tid == 0) out[0] = v * (1.0f / TOP_K);
    }
}

// ---------------------------------------------------------------------------
// Launch (3 kernels)
// ---------------------------------------------------------------------------
extern "C" void kernel_launch(void* const* d_in, const int* in_sizes, int n_in,
                              void* d_out, int out_size) {
    const float* data_in = (const float*)d_in[0];
    const float* tmat    = (const float*)d_in[1];
    const float* ref     = (const float*)d_in[2];
    const float* psuedo  = (const float*)d_in[3];
    float* out = (float*)d_out;

    project_partial<<<PROJ_BLOCKS, N_PC>>>(data_in, tmat);
    dist_topk_kernel<<<BLOCKS, THREADS>>>(ref);
    merge_kernel<<<1, MERGE_T>>>(psuedo, out);
}

// round 14
// speedup vs baseline: 2.5858x; 1.0316x over previous
#include <cuda_runtime.h>
#include <float.h>

#define N_REF   500000
#define N_PC    128
#define N_FEAT  2000
#define TOP_K   16

#define BLOCKS           592
#define THREADS          256
#define WARPS_PER_BLOCK  (THREADS / 32)
#define TOTAL_WARPS      (BLOCKS * WARPS_PER_BLOCK)   // 4736
#define N_CAND           (BLOCKS * TOP_K)             // 9472

#define PROJ_BLOCKS      50
#define FEAT_PER_BLOCK   (N_FEAT / PROJ_BLOCKS)       // 40
#define PROJ_Y           4
#define FEAT_PER_Y       (FEAT_PER_BLOCK / PROJ_Y)    // 10

#define MERGE_T          1024
#define MERGE_ROUNDS     ((N_CAND + MERGE_T - 1) / MERGE_T)   // 10
#define SURV_CAP         2048
#define MIN_PAD          608                          // 19 warps * 32
#define N_LISTS          19

// Scratch (no cudaMalloc allowed)
__device__ float g_qpart[PROJ_BLOCKS * N_PC];
__device__ float g_cand_d[N_CAND];
__device__ int   g_cand_i[N_CAND];
__device__ float g_bmin[BLOCKS];      // per-block minimum (compact, coalesced)

// ---------------------------------------------------------------------------
// Warp-distributed top-16 insert. Lane l (<16) holds the l-th smallest
// (dval, divx). v must be warp-uniform. ~7 instructions, no serial chain.
// ---------------------------------------------------------------------------
__device__ __forceinline__ void warp_insert16(float& dval, int& divx,
                                              float& kmax, int lane,
                                              float v, int id) {
    unsigned m = __ballot_sync(0xFFFFFFFFu, dval < v);
    int pos = __popc(m & 0xFFFFu);
    float up_d = __shfl_up_sync(0xFFFFFFFFu, dval, 1);
    int   up_i = __shfl_up_sync(0xFFFFFFFFu, divx, 1);
    if (lane >= pos) {
        dval = (lane == pos) ? v  : up_d;
        divx = (lane == pos) ? id : up_i;
    }
    kmax = __shfl_sync(0xFFFFFFFFu, dval, 15);
}

// ---------------------------------------------------------------------------
// Warp bitonic sort of 32 floats (ascending by lane), values only.
// ---------------------------------------------------------------------------
__device__ __forceinline__ void bitonic32v(float& v, int lane) {
    #pragma unroll
    for (int k = 2; k <= 32; k <<= 1) {
        #pragma unroll
        for (int j = k >> 1; j > 0; j >>= 1) {
            float ov = __shfl_xor_sync(0xFFFFFFFFu, v, j);
            bool up      = ((lane & k) == 0);
            bool lower   = ((lane & j) == 0);
            bool takeMin = (lower == up);
            bool sel = takeMin ? (ov < v) : (ov > v);
            v = sel ? ov : v;
        }
    }
}

// Bitonic MERGE of a 32-lane bitonic sequence -> ascending (5 stages).
__device__ __forceinline__ void bitonic_merge32(float& v, int lane) {
    #pragma unroll
    for (int j = 16; j > 0; j >>= 1) {
        float ov = __shfl_xor_sync(0xFFFFFFFFu, v, j);
        v = ((lane & j) == 0) ? fminf(v, ov) : fmaxf(v, ov);
    }
}

// ---------------------------------------------------------------------------
// Kernel A: partial query projection. Block b covers 40 features, split
// across 4 y-slices of 10 -> per-thread chain of 10 independent loads
// (MLP=10) instead of 40; 16 warps/block to hide DRAM latency. Shared
// reduce over y writes the SAME g_qpart layout as before.
// ---------------------------------------------------------------------------
__global__ void __launch_bounds__(N_PC * PROJ_Y)
project_partial(const float* __restrict__ data_in,
                const float* __restrict__ tmat) {
    const int j  = threadIdx.x;          // 0..127 (PC index)
    const int y  = threadIdx.y;          // 0..3
    const int b  = blockIdx.x;
    const int k0 = b * FEAT_PER_BLOCK + y * FEAT_PER_Y;

    float acc = 0.0f;
    #pragma unroll
    for (int k = k0; k < k0 + FEAT_PER_Y; k++)
        acc += data_in[k] * tmat[k * N_PC + j];   // coalesced over j

    __shared__ float sred[PROJ_Y][N_PC];
    sred[y][j] = acc;
    __syncthreads();
    if (y == 0) {
        g_qpart[b * N_PC + j] = sred[0][j] + sred[1][j] + sred[2][j] + sred[3][j];
    }
}

// ---------------------------------------------------------------------------
// Kernel B (UNCHANGED from R13 best): [prologue] reduce 50 projection
// partials -> shared; [mainloop] warp/row, 4-row unroll, register
// double-buffer prefetch, warp-distributed top-16; [tail] parallel
// rank-select block top-16 + compact g_bmin write.
// ---------------------------------------------------------------------------
__global__ void __launch_bounds__(THREADS)
dist_topk_kernel(const float* __restrict__ ref) {
    const int tid  = threadIdx.x;
    const int lane = tid & 31;
    const int wid  = tid >> 5;
    const int gw   = blockIdx.x * WARPS_PER_BLOCK + wid;

    // ---- prologue: finish query projection into shared ----
    __shared__ __align__(16) float sq[N_PC];
    if (tid < N_PC) {
        float acc = 0.0f;
        #pragma unroll
        for (int b = 0; b < PROJ_BLOCKS; b++)
            acc += g_qpart[b * N_PC + tid];
        sq[tid] = acc;
    }
    __syncthreads();
    const float4 q = reinterpret_cast<const float4*>(sq)[lane];

    const int chunk = (N_REF + TOTAL_WARPS - 1) / TOTAL_WARPS;  // 106
    int start = gw * chunk;
    int end   = start + chunk;
    if (start > N_REF) start = N_REF;
    if (end   > N_REF) end   = N_REF;

    float dval = FLT_MAX;
    int   divx = 0;
    float kmax = FLT_MAX;

    const float4* __restrict__ ref4 = reinterpret_cast<const float4*>(ref);

    const int nIter = (end - start) / 4;
    int r = start;

    float4 A0, A1, A2, A3;
    if (nIter > 0) {
        A0 = __ldcs(ref4 + (size_t)(r + 0) * (N_PC / 4) + lane);
        A1 = __ldcs(ref4 + (size_t)(r + 1) * (N_PC / 4) + lane);
        A2 = __ldcs(ref4 + (size_t)(r + 2) * (N_PC / 4) + lane);
        A3 = __ldcs(ref4 + (size_t)(r + 3) * (N_PC / 4) + lane);
    }

    for (int it = 0; it < nIter; it++) {
        float4 B0, B1, B2, B3;
        if (it + 1 < nIter) {
            int rn = r + 4;
            B0 = __ldcs(ref4 + (size_t)(rn + 0) * (N_PC / 4) + lane);
            B1 = __ldcs(ref4 + (size_t)(rn + 1) * (N_PC / 4) + lane);
            B2 = __ldcs(ref4 + (size_t)(rn + 2) * (N_PC / 4) + lane);
            B3 = __ldcs(ref4 + (size_t)(rn + 3) * (N_PC / 4) + lane);
        }

        float s0 = fabsf(A0.x - q.x) + fabsf(A0.y - q.y) + fabsf(A0.z - q.z) + fabsf(A0.w - q.w);
        float s1 = fabsf(A1.x - q.x) + fabsf(A1.y - q.y) + fabsf(A1.z - q.z) + fabsf(A1.w - q.w);
        float s2 = fabsf(A2.x - q.x) + fabsf(A2.y - q.y) + fabsf(A2.z - q.z) + fabsf(A2.w - q.w);
        float s3 = fabsf(A3.x - q.x) + fabsf(A3.y - q.y) + fabsf(A3.z - q.z) + fabsf(A3.w - q.w);

        #pragma unroll
        for (int off = 16; off > 0; off >>= 1) {
            s0 += __shfl_xor_sync(0xFFFFFFFFu, s0, off);
            s1 += __shfl_xor_sync(0xFFFFFFFFu, s1, off);
            s2 += __shfl_xor_sync(0xFFFFFFFFu, s2, off);
            s3 += __shfl_xor_sync(0xFFFFFFFFu, s3, off);
        }
        if (s0 < kmax) warp_insert16(dval, divx, kmax, lane, s0, r + 0);
        if (s1 < kmax) warp_insert16(dval, divx, kmax, lane, s1, r + 1);
        if (s2 < kmax) warp_insert16(dval, divx, kmax, lane, s2, r + 2);
        if (s3 < kmax) warp_insert16(dval, divx, kmax, lane, s3, r + 3);

        A0 = B0; A1 = B1; A2 = B2; A3 = B3;
        r += 4;
    }
    for (; r < end; r++) {
        float4 a0 = __ldcs(ref4 + (size_t)r * (N_PC / 4) + lane);
        float s0 = fabsf(a0.x - q.x) + fabsf(a0.y - q.y) + fabsf(a0.z - q.z) + fabsf(a0.w - q.w);
        #pragma unroll
        for (int off = 16; off > 0; off >>= 1)
            s0 += __shfl_xor_sync(0xFFFFFFFFu, s0, off);
        if (s0 < kmax) warp_insert16(dval, divx, kmax, lane, s0, r);
    }

    __shared__ float sbd[WARPS_PER_BLOCK * TOP_K];   // 128
    __shared__ int   sbi[WARPS_PER_BLOCK * TOP_K];
    if (lane < TOP_K) {
        sbd[wid * TOP_K + lane] = dval;
        sbi[wid * TOP_K + lane] = divx;
    }
    __syncthreads();

    if (tid < 128) {
        float v  = sbd[tid];
        int   id = sbi[tid];
        int rank = 0;
        #pragma unroll 8
        for (int j = 0; j < 128; j++) {
            float o = sbd[j];
            rank += (o < v) || (o == v && j < tid);
        }
        if (rank < TOP_K) {
            g_cand_d[blockIdx.x * TOP_K + rank] = v;
            g_cand_i[blockIdx.x * TOP_K + rank] = id;
        }
        if (rank == 0) g_bmin[blockIdx.x] = v;   // compact block minimum
    }
}

// ---------------------------------------------------------------------------
// Kernel C (UNCHANGED from R13): merge. Loads hoisted; tau = exact 16th of
// 592 block minima via bitonic merge tree; warp-aggregated filter append;
// rank-select + gather + mean.
// ---------------------------------------------------------------------------
__global__ void __launch_bounds__(MERGE_T)
merge_kernel(const float* __restrict__ psuedo,
             float* __restrict__ out) {
    const int tid  = threadIdx.x;
    const int lane = tid & 31;
    const int wid  = tid >> 5;

    __shared__ float s_a[N_LISTS * TOP_K];   // 304
    __shared__ float s_b[N_LISTS * TOP_K];
    __shared__ int   s_cnt;
    __shared__ float s_d[SURV_CAP];
    __shared__ int   s_c[SURV_CAP];
    __shared__ float s_sel[TOP_K];

    if (tid == 0) s_cnt = 0;

    // ---- issue ALL global loads up front ----
    float vb[MERGE_ROUNDS];
    #pragma unroll
    for (int t = 0; t < MERGE_ROUNDS; t++) {
        int c = tid + t * MERGE_T;
        vb[t] = (c < N_CAND) ? g_cand_d[c] : FLT_MAX;
    }
    float vmin = (tid < BLOCKS) ? g_bmin[tid] : FLT_MAX;   // coalesced

    // ---- phase 1a: per-warp bitonic sort-32, keep sorted 16 ----
    if (tid < MIN_PAD) {               // 19 full warps
        bitonic32v(vmin, lane);
        if (lane < TOP_K) s_a[wid * TOP_K + lane] = vmin;
    }
    __syncthreads();

    // ---- phase 1b: bitonic merge tree, 19 lists -> 1 (ping-pong) ----
    {
        float* src = s_a;
        float* dst = s_b;
        int n = N_LISTS;
        while (n > 1) {
            int half = n >> 1;
            if (wid < half) {
                float v = (lane < TOP_K)
                        ? src[(2 * wid) * TOP_K + lane]
                        : src[(2 * wid + 1) * TOP_K + (31 - lane)];
                bitonic_merge32(v, lane);
                if (lane < TOP_K) dst[wid * TOP_K + lane] = v;
            } else if ((n & 1) && wid == half) {
                if (lane < TOP_K)
                    dst[half * TOP_K + lane] = src[(n - 1) * TOP_K + lane];
            }
            __syncthreads();
            n = half + (n & 1);
            float* tmp = src; src = dst; dst = tmp;
        }
        if (tid == 0) s_sel[0] = src[TOP_K - 1];   // stash tau
    }
    __syncthreads();
    const float tau = s_sel[0];

    // ---- phase 2: threshold filter with warp-aggregated append ----
    #pragma unroll
    for (int t = 0; t < MERGE_ROUNDS; t++) {
        int c = tid + t * MERGE_T;
        bool pred = (vb[t] <= tau);
        unsigned m = __ballot_sync(0xFFFFFFFFu, pred);
        if (m) {
            int base = 0;
            if (lane == 0) base = atomicAdd(&s_cnt, __popc(m));
            base = __shfl_sync(0xFFFFFFFFu, base, 0);
            if (pred) {
                int pos = base + __popc(m & ((1u << lane) - 1u));
                if (pos < SURV_CAP) {
                    s_d[pos] = vb[t];
                    s_c[pos] = c;
                }
            }
        }
    }
    __syncthreads();
    const int cnt = (s_cnt < SURV_CAP) ? s_cnt : SURV_CAP;

    // ---- phase 3: rank-select top-16 of survivors, gather, mean ----
    if (tid < cnt) {
        float v = s_d[tid];
        int   c = s_c[tid];
        int rank = 0;
        for (int j = 0; j < cnt; j++) {
            float o = s_d[j];
            rank += (o < v) || (o == v && s_c[j] < c);
        }
        if (rank < TOP_K) s_sel[rank] = psuedo[g_cand_i[c]];
    }
    __syncthreads();

    if (tid < 32) {
        float v = (tid < TOP_K) ? s_sel[tid] : 0.0f;
        #pragma unroll
        for (int off = 16; off > 0; off >>= 1)
            v += __shfl_xor_sync(0xFFFFFFFFu, v, off);
        if (tid == 0) out[0] = v * (1.0f / TOP_K);
    }
}

// ---------------------------------------------------------------------------
// Launch (3 kernels)
// ---------------------------------------------------------------------------
extern "C" void kernel_launch(void* const* d_in, const int* in_sizes, int n_in,
                              void* d_out, int out_size) {
    const float* data_in = (const float*)d_in[0];
    const float* tmat    = (const float*)d_in[1];
    const float* ref     = (const float*)d_in[2];
    const float* psuedo  = (const float*)d_in[3];
    float* out = (float*)d_out;

    dim3 pb(N_PC, PROJ_Y);
    project_partial<<<PROJ_BLOCKS, pb>>>(data_in, tmat);
    dist_topk_kernel<<<BLOCKS, THREADS>>>(ref);
    merge_kernel<<<1, MERGE_T>>>(psuedo, out);
}